// round 3
// baseline (speedup 1.0000x reference)
#include <cuda_runtime.h>

// Shapes (fixed for this problem)
#define BB   16
#define CC   128
#define HIDD 256
#define HH   80
#define WW   80
#define PP   6400      // HH*WW
#define NGG  8
#define EPSV 1e-5f

// ---------------- device scratch (static: allocation-free) ----------------
__device__ float g_s[(size_t)BB * CC * PP];        // conv3x3 output (pre-BN)
__device__ float g_h[(size_t)BB * HIDD * PP];      // expert hidden (pre-GN1)
__device__ float g_y[(size_t)BB * CC * PP];        // expert out (pre-GN2)

__device__ float g_bn_sum[CC], g_bn_sq[CC];
__device__ float g_bn_scale[CC], g_bn_shift[CC];
__device__ float g_gn1_sum[BB * NGG], g_gn1_sq[BB * NGG];
__device__ float g_gn1_mr[BB * NGG * 2];           // mean, rstd interleaved
__device__ float g_gn2_sum[BB * NGG], g_gn2_sq[BB * NGG];
__device__ float g_gn2_mr[BB * NGG * 2];

// ---------------- K0: zero accumulators (graph replays must be deterministic) ----
__global__ void k_zero() {
    int t = threadIdx.x;
    if (t < CC) { g_bn_sum[t] = 0.f; g_bn_sq[t] = 0.f; }
    if (t < BB * NGG) {
        g_gn1_sum[t] = 0.f; g_gn1_sq[t] = 0.f;
        g_gn2_sum[t] = 0.f; g_gn2_sq[t] = 0.f;
    }
}

// ---------------- K1: conv3x3 (SAME pad) + BN partial sums --------------------
// Tile: 64 out-channels x (8 rows x 16 cols) pixels. 256 threads,
// each thread computes 4 oc x 8 px. K loop over input channels in chunks of 8.
__global__ __launch_bounds__(256) void k_conv(const float* __restrict__ x,
                                              const float* __restrict__ w) {
    __shared__ float xs[8 * 190];        // [cc][10 rows][19 pad cols] (18 used)
    __shared__ float ws[8 * 9 * 64];     // [cc][tap][oc64]
    __shared__ float ssum[64], ssq[64];

    const int tid  = threadIdx.x;
    const int b    = blockIdx.z;
    const int oc0  = blockIdx.x * 64;
    const int ty   = blockIdx.y / 5, tx = blockIdx.y % 5;
    const int row0 = ty * 8, col0 = tx * 16;
    const int ocg  = tid >> 4;           // 0..15
    const int pg   = tid & 15;
    const int prow = pg >> 1;            // 0..7
    const int pcol = (pg & 1) * 8;       // 0 or 8

    if (tid < 64) { ssum[tid] = 0.f; ssq[tid] = 0.f; }

    float acc[4][8];
#pragma unroll
    for (int o = 0; o < 4; o++)
#pragma unroll
        for (int j = 0; j < 8; j++) acc[o][j] = 0.f;

    const float* xb = x + (size_t)b * CC * PP;

    for (int c0 = 0; c0 < CC; c0 += 8) {
        // stage input halo tile: 8 ch x 10 x 18
        for (int i = tid; i < 8 * 10 * 18; i += 256) {
            int cc  = i / 180;
            int rem = i - cc * 180;
            int r   = rem / 18;
            int col = rem - r * 18;
            int gr = row0 + r - 1, gc = col0 + col - 1;
            float v = 0.f;
            if ((unsigned)gr < 80u && (unsigned)gc < 80u)
                v = xb[(size_t)(c0 + cc) * PP + gr * 80 + gc];
            xs[cc * 190 + r * 19 + col] = v;
        }
        // stage weights: 8 ch x 9 taps x 64 oc (oc contiguous for float4)
        for (int i = tid; i < 8 * 9 * 64; i += 256) {
            int cc  = i / 576;
            int rem = i - cc * 576;
            int t   = rem >> 6;
            int o   = rem & 63;
            ws[cc * 576 + t * 64 + o] = w[((size_t)(oc0 + o) * CC + c0 + cc) * 9 + t];
        }
        __syncthreads();

        for (int cc = 0; cc < 8; cc++) {
#pragma unroll
            for (int kh = 0; kh < 3; kh++) {
                float xr[10];
#pragma unroll
                for (int j = 0; j < 10; j++)
                    xr[j] = xs[cc * 190 + (prow + kh) * 19 + pcol + j];
#pragma unroll
                for (int kw = 0; kw < 3; kw++) {
                    float4 wv = *(const float4*)&ws[cc * 576 + (kh * 3 + kw) * 64 + ocg * 4];
#pragma unroll
                    for (int j = 0; j < 8; j++) {
                        acc[0][j] = fmaf(wv.x, xr[j + kw], acc[0][j]);
                        acc[1][j] = fmaf(wv.y, xr[j + kw], acc[1][j]);
                        acc[2][j] = fmaf(wv.z, xr[j + kw], acc[2][j]);
                        acc[3][j] = fmaf(wv.w, xr[j + kw], acc[3][j]);
                    }
                }
            }
        }
        __syncthreads();
    }

    // store s + block-level BN partial sums
    const int row = row0 + prow, col = col0 + pcol;
#pragma unroll
    for (int o = 0; o < 4; o++) {
        int oc = oc0 + ocg * 4 + o;
        float* sp = g_s + ((size_t)b * CC + oc) * PP + row * 80 + col;
        *(float4*)sp       = make_float4(acc[o][0], acc[o][1], acc[o][2], acc[o][3]);
        *(float4*)(sp + 4) = make_float4(acc[o][4], acc[o][5], acc[o][6], acc[o][7]);
        float s = 0.f, q = 0.f;
#pragma unroll
        for (int j = 0; j < 8; j++) { s += acc[o][j]; q += acc[o][j] * acc[o][j]; }
        atomicAdd(&ssum[ocg * 4 + o], s);
        atomicAdd(&ssq[ocg * 4 + o], q);
    }
    __syncthreads();
    if (tid < 64) {
        atomicAdd(&g_bn_sum[oc0 + tid], ssum[tid]);
        atomicAdd(&g_bn_sq[oc0 + tid], ssq[tid]);
    }
}

// ---------------- stat finalize kernels ----------------
__global__ void k_fin_bn(const float* __restrict__ gamma, const float* __restrict__ beta) {
    int t = threadIdx.x; // 128
    const float inv = 1.f / (float)(BB * PP);
    float m = g_bn_sum[t] * inv;
    float v = g_bn_sq[t] * inv - m * m;
    float r = rsqrtf(v + EPSV);
    float sc = gamma[t] * r;
    g_bn_scale[t] = sc;
    g_bn_shift[t] = beta[t] - m * sc;
}

__global__ void k_fin_gn1() {
    int t = threadIdx.x; // 128 = BB*NGG
    const float inv = 1.f / (float)((HIDD / NGG) * PP); // 32*6400
    float m = g_gn1_sum[t] * inv;
    float v = g_gn1_sq[t] * inv - m * m;
    g_gn1_mr[2 * t]     = m;
    g_gn1_mr[2 * t + 1] = rsqrtf(v + EPSV);
}

__global__ void k_fin_gn2() {
    int t = threadIdx.x; // 128
    const float inv = 1.f / (float)((CC / NGG) * PP); // 16*6400
    float m = g_gn2_sum[t] * inv;
    float v = g_gn2_sq[t] * inv - m * m;
    g_gn2_mr[2 * t]     = m;
    g_gn2_mr[2 * t + 1] = rsqrtf(v + EPSV);
}

// ---------------- K3: expert GEMM1 (h = w1[e] @ x_b) + GN1 partial sums -------
// Per-batch dynamic expert: block early-exits if indices[b]==0.
// Tile 64 M x 128 N, K chunk 16. 256 threads, each 4x8.
__global__ __launch_bounds__(256) void k_gemm1(const float* __restrict__ x,
                                               const int* __restrict__ indices,
                                               const float* __restrict__ w1) {
    const int b = blockIdx.z;
    const int idx = indices[b];
    if (idx == 0) return;
    const int e = idx - 1;

    __shared__ float As[16 * 68];   // [k][m64] padded
    __shared__ float Bs[16 * 128];  // [k][n128]
    __shared__ float gsum[2], gsq[2];

    const int tid = threadIdx.x;
    const int mg = tid >> 4, ng = tid & 15;
    const int m0 = blockIdx.y * 64;
    const int nb = blockIdx.x * 128;
    if (tid < 2) { gsum[tid] = 0.f; gsq[tid] = 0.f; }

    float acc[4][8];
#pragma unroll
    for (int o = 0; o < 4; o++)
#pragma unroll
        for (int j = 0; j < 8; j++) acc[o][j] = 0.f;

    const float* wbase = w1 + (size_t)e * HIDD * CC;
    const float* xb    = x + (size_t)b * CC * PP;

    for (int k0 = 0; k0 < CC; k0 += 16) {
        for (int i = tid; i < 1024; i += 256) {
            int m = i >> 4, kk = i & 15;
            As[kk * 68 + m] = wbase[(size_t)(m0 + m) * CC + k0 + kk];
        }
        for (int i = tid; i < 2048; i += 256) {
            int kk = i >> 7, n = i & 127;
            Bs[kk * 128 + n] = xb[(size_t)(k0 + kk) * PP + nb + n];
        }
        __syncthreads();
#pragma unroll
        for (int kk = 0; kk < 16; kk++) {
            float4 av  = *(const float4*)&As[kk * 68 + mg * 4];
            float4 bv0 = *(const float4*)&Bs[kk * 128 + ng * 8];
            float4 bv1 = *(const float4*)&Bs[kk * 128 + ng * 8 + 4];
            float a[4]  = {av.x, av.y, av.z, av.w};
            float bb[8] = {bv0.x, bv0.y, bv0.z, bv0.w, bv1.x, bv1.y, bv1.z, bv1.w};
#pragma unroll
            for (int o = 0; o < 4; o++)
#pragma unroll
                for (int j = 0; j < 8; j++)
                    acc[o][j] = fmaf(a[o], bb[j], acc[o][j]);
        }
        __syncthreads();
    }

    // store h + GN1 stats (raw h; GN normalizes raw values)
    float lsum = 0.f, lsq = 0.f;
#pragma unroll
    for (int o = 0; o < 4; o++) {
        float* hp = g_h + ((size_t)b * HIDD + m0 + mg * 4 + o) * PP + nb + ng * 8;
        *(float4*)hp       = make_float4(acc[o][0], acc[o][1], acc[o][2], acc[o][3]);
        *(float4*)(hp + 4) = make_float4(acc[o][4], acc[o][5], acc[o][6], acc[o][7]);
#pragma unroll
        for (int j = 0; j < 8; j++) { lsum += acc[o][j]; lsq += acc[o][j] * acc[o][j]; }
    }
#pragma unroll
    for (int off = 16; off > 0; off >>= 1) {
        lsum += __shfl_down_sync(0xffffffffu, lsum, off);
        lsq  += __shfl_down_sync(0xffffffffu, lsq, off);
    }
    if ((tid & 31) == 0) {
        int grel = (mg * 4) >> 5;  // uniform within warp
        atomicAdd(&gsum[grel], lsum);
        atomicAdd(&gsq[grel], lsq);
    }
    __syncthreads();
    if (tid < 2) {
        int g = (m0 >> 5) + tid;
        atomicAdd(&g_gn1_sum[b * NGG + g], gsum[tid]);
        atomicAdd(&g_gn1_sq[b * NGG + g], gsq[tid]);
    }
}

// ---------------- K5: expert GEMM2 (y = w2[e] @ silu(GN1(h))) + GN2 sums ------
__global__ __launch_bounds__(256) void k_gemm2(const int* __restrict__ indices,
                                               const float* __restrict__ w2,
                                               const float* __restrict__ g1,
                                               const float* __restrict__ b1) {
    const int b = blockIdx.z;
    const int idx = indices[b];
    if (idx == 0) return;
    const int e = idx - 1;

    __shared__ float As[16 * 68];
    __shared__ float Bs[16 * 128];
    __shared__ float sa[HIDD], sb[HIDD];
    __shared__ float gsum[4], gsq[4];

    const int tid = threadIdx.x;
    const int mg = tid >> 4, ng = tid & 15;
    const int m0 = blockIdx.y * 64;
    const int nb = blockIdx.x * 128;

    { // per-k GN1 affine coefficients (fold mean/rstd/gamma/beta)
        int k = tid;            // 256 threads == HIDD
        int gg = k >> 5;
        float mean = g_gn1_mr[(b * NGG + gg) * 2];
        float rstd = g_gn1_mr[(b * NGG + gg) * 2 + 1];
        float a = rstd * g1[e * HIDD + k];
        sa[k] = a;
        sb[k] = b1[e * HIDD + k] - mean * a;
    }
    if (tid < 4) { gsum[tid] = 0.f; gsq[tid] = 0.f; }
    __syncthreads();

    float acc[4][8];
#pragma unroll
    for (int o = 0; o < 4; o++)
#pragma unroll
        for (int j = 0; j < 8; j++) acc[o][j] = 0.f;

    const float* wbase = w2 + (size_t)e * CC * HIDD;
    const float* hb    = g_h + (size_t)b * HIDD * PP;

    for (int k0 = 0; k0 < HIDD; k0 += 16) {
        for (int i = tid; i < 1024; i += 256) {
            int m = i >> 4, kk = i & 15;
            As[kk * 68 + m] = wbase[(size_t)(m0 + m) * HIDD + k0 + kk];
        }
        for (int i = tid; i < 2048; i += 256) {
            int kk = i >> 7, n = i & 127;
            int kg = k0 + kk;
            float t = fmaf(hb[(size_t)kg * PP + nb + n], sa[kg], sb[kg]);
            Bs[kk * 128 + n] = t / (1.f + expf(-t));   // SiLU
        }
        __syncthreads();
#pragma unroll
        for (int kk = 0; kk < 16; kk++) {
            float4 av  = *(const float4*)&As[kk * 68 + mg * 4];
            float4 bv0 = *(const float4*)&Bs[kk * 128 + ng * 8];
            float4 bv1 = *(const float4*)&Bs[kk * 128 + ng * 8 + 4];
            float a[4]  = {av.x, av.y, av.z, av.w};
            float bb[8] = {bv0.x, bv0.y, bv0.z, bv0.w, bv1.x, bv1.y, bv1.z, bv1.w};
#pragma unroll
            for (int o = 0; o < 4; o++)
#pragma unroll
                for (int j = 0; j < 8; j++)
                    acc[o][j] = fmaf(a[o], bb[j], acc[o][j]);
        }
        __syncthreads();
    }

    float lsum = 0.f, lsq = 0.f;
#pragma unroll
    for (int o = 0; o < 4; o++) {
        float* yp = g_y + ((size_t)b * CC + m0 + mg * 4 + o) * PP + nb + ng * 8;
        *(float4*)yp       = make_float4(acc[o][0], acc[o][1], acc[o][2], acc[o][3]);
        *(float4*)(yp + 4) = make_float4(acc[o][4], acc[o][5], acc[o][6], acc[o][7]);
#pragma unroll
        for (int j = 0; j < 8; j++) { lsum += acc[o][j]; lsq += acc[o][j] * acc[o][j]; }
    }
#pragma unroll
    for (int off = 16; off > 0; off >>= 1) {
        lsum += __shfl_down_sync(0xffffffffu, lsum, off);
        lsq  += __shfl_down_sync(0xffffffffu, lsq, off);
    }
    if ((tid & 31) == 0) {
        int grel = mg >> 2;   // 16-channel groups; uniform within warp
        atomicAdd(&gsum[grel], lsum);
        atomicAdd(&gsq[grel], lsq);
    }
    __syncthreads();
    if (tid < 4) {
        int g = (m0 >> 4) + tid;
        atomicAdd(&g_gn2_sum[b * NGG + g], gsum[tid]);
        atomicAdd(&g_gn2_sq[b * NGG + g], gsq[tid]);
    }
}

// ---------------- K7: combine: out = silu(BN(s)) + w_b * (GN2(y) or x) --------
__global__ __launch_bounds__(256) void k_combine(const float* __restrict__ x,
                                                 const float* __restrict__ weights,
                                                 const int* __restrict__ indices,
                                                 const float* __restrict__ g2,
                                                 const float* __restrict__ b2,
                                                 float* __restrict__ out) {
    const int blk = blockIdx.x;
    const int b = blk >> 7, c = blk & 127;
    const int idx = indices[b];
    const float wb = weights[b];
    const float sc = g_bn_scale[c], sh = g_bn_shift[c];

    float a2, c2;
    if (idx > 0) {
        int e = idx - 1;
        int g = c >> 4;
        float mean = g_gn2_mr[(b * NGG + g) * 2];
        float rstd = g_gn2_mr[(b * NGG + g) * 2 + 1];
        float ga = rstd * g2[e * CC + c];
        a2 = ga * wb;
        c2 = (b2[e * CC + c] - mean * ga) * wb;
    } else {
        a2 = wb;   // identity expert
        c2 = 0.f;
    }

    const size_t base = ((size_t)b * CC + c) * PP;
    const float4* sp = (const float4*)(g_s + base);
    const float4* rp = (idx > 0) ? (const float4*)(g_y + base) : (const float4*)(x + base);
    float4* op = (float4*)(out + base);

    for (int i = threadIdx.x; i < PP / 4; i += 256) {
        float4 sv = sp[i];
        float4 rv = rp[i];
        float4 o;
        float t;
        t = fmaf(sv.x, sc, sh); o.x = t / (1.f + expf(-t)) + fmaf(rv.x, a2, c2);
        t = fmaf(sv.y, sc, sh); o.y = t / (1.f + expf(-t)) + fmaf(rv.y, a2, c2);
        t = fmaf(sv.z, sc, sh); o.z = t / (1.f + expf(-t)) + fmaf(rv.z, a2, c2);
        t = fmaf(sv.w, sc, sh); o.w = t / (1.f + expf(-t)) + fmaf(rv.w, a2, c2);
        op[i] = o;
    }
}

// ---------------- launch ----------------
extern "C" void kernel_launch(void* const* d_in, const int* in_sizes, int n_in,
                              void* d_out, int out_size) {
    const float* x        = (const float*)d_in[0];   // [16,128,80,80]
    const float* weights  = (const float*)d_in[1];   // [16]
    const int*   indices  = (const int*)d_in[2];     // [16]
    const float* shared_w = (const float*)d_in[3];   // [128,128,3,3]
    const float* bn_gamma = (const float*)d_in[4];   // [128]
    const float* bn_beta  = (const float*)d_in[5];   // [128]
    const float* w1       = (const float*)d_in[6];   // [3,256,128]
    const float* g1       = (const float*)d_in[7];   // [3,256]
    const float* b1       = (const float*)d_in[8];   // [3,256]
    const float* w2       = (const float*)d_in[9];   // [3,128,256]
    const float* g2       = (const float*)d_in[10];  // [3,128]
    const float* b2       = (const float*)d_in[11];  // [3,128]
    float* out = (float*)d_out;

    k_zero<<<1, 256>>>();
    k_conv<<<dim3(2, 50, BB), 256>>>(x, shared_w);
    k_gemm1<<<dim3(50, 4, BB), 256>>>(x, indices, w1);
    k_fin_bn<<<1, 128>>>(bn_gamma, bn_beta);
    k_fin_gn1<<<1, 128>>>();
    k_gemm2<<<dim3(50, 2, BB), 256>>>(indices, w2, g1, b1);
    k_fin_gn2<<<1, 128>>>();
    k_combine<<<BB * CC, 256>>>(x, weights, indices, g2, b2, out);
}